// round 1
// baseline (speedup 1.0000x reference)
#include <cuda_runtime.h>

// Problem dims (fixed by the dataset)
#define N_BATCH 32
#define B_OBJ   36
#define D_DIM   2048
#define Q_DIM   1024
#define NB      (N_BATCH * B_OBJ)   // 1152

// Scratch (device globals — no allocation allowed in kernel_launch)
__device__ float g_qe[N_BATCH * D_DIM];   // relu(q @ W3 + b3)   (32, 2048)
__device__ float g_u [NB * D_DIM];        // v * qe              (1152, 2048)
__device__ float g_g [NB * D_DIM];        // u @ W1              (1152, 2048)
__device__ float g_x [NB * D_DIM];        // sum_j relu(g_i+g_j+b1)

// ---------------------------------------------------------------------------
// Kernel 1: qe[n,d] = relu(sum_k q[n,k] * W3[k,d] + b3[d])
// M=32 is too thin for the block GEMM; one thread per output element,
// W3 (8 MB) is L2-resident after first pass.
// ---------------------------------------------------------------------------
__global__ void qe_kernel(const float* __restrict__ q,
                          const float* __restrict__ W3,
                          const float* __restrict__ b3) {
    int idx = blockIdx.x * blockDim.x + threadIdx.x;
    if (idx >= N_BATCH * D_DIM) return;
    int n = idx / D_DIM;
    int d = idx % D_DIM;
    const float* qr = q + n * Q_DIM;
    float acc = 0.f;
    #pragma unroll 8
    for (int k = 0; k < Q_DIM; k++) {
        acc += qr[k] * W3[k * D_DIM + d];
    }
    g_qe[idx] = fmaxf(acc + b3[d], 0.f);
}

// ---------------------------------------------------------------------------
// Kernel 2: u[n,i,d] = v[n,i,d] * qe[n,d]
// ---------------------------------------------------------------------------
__global__ void u_kernel(const float* __restrict__ v) {
    int idx = blockIdx.x * blockDim.x + threadIdx.x;
    if (idx >= NB * D_DIM) return;
    int row = idx / D_DIM;        // n*B + i
    int d   = idx % D_DIM;
    int n   = row / B_OBJ;
    g_u[idx] = v[idx] * g_qe[n * D_DIM + d];
}

// ---------------------------------------------------------------------------
// Kernel 3/5: C = [relu](A @ B [+ bias]) ; A: MxK row-major, B: KxN row-major.
// Classic 128x128x8 register-tiled SGEMM, TM=TN=8, 256 threads.
// N % BN == 0 and K % BK == 0 required (holds: N=2048, K=2048).
// ---------------------------------------------------------------------------
template<int BM, int BN, int BK, int TM, int TN, bool RELU, bool BIAS>
__global__ __launch_bounds__((BM / TM) * (BN / TN))
void sgemm_kernel(int M, int N, int K,
                  const float* __restrict__ A,
                  const float* __restrict__ B,
                  const float* __restrict__ bias,
                  float* __restrict__ C) {
    constexpr int THREADS = (BM / TM) * (BN / TN);
    __shared__ float As[BK][BM];  // transposed A tile
    __shared__ float Bs[BK][BN];

    const int tid      = threadIdx.x;
    const int blockCol = blockIdx.x;   // along N
    const int blockRow = blockIdx.y;   // along M

    const int threadCol = tid % (BN / TN);
    const int threadRow = tid / (BN / TN);

    float acc[TM][TN];
    #pragma unroll
    for (int m = 0; m < TM; m++)
        #pragma unroll
        for (int n = 0; n < TN; n++) acc[m][n] = 0.f;

    const float* Aptr = A + (long)blockRow * BM * K;
    const float* Bptr = B + blockCol * BN;

    for (int k0 = 0; k0 < K; k0 += BK) {
        // Load A tile (BM x BK) -> transposed into As[BK][BM]
        #pragma unroll
        for (int i = tid * 4; i < BM * BK; i += THREADS * 4) {
            int row = i / BK;
            int col = i % BK;
            float4 t;
            int grow = blockRow * BM + row;
            if (grow < M) {
                t = *reinterpret_cast<const float4*>(&Aptr[(long)row * K + k0 + col]);
            } else {
                t = make_float4(0.f, 0.f, 0.f, 0.f);
            }
            As[col + 0][row] = t.x;
            As[col + 1][row] = t.y;
            As[col + 2][row] = t.z;
            As[col + 3][row] = t.w;
        }
        // Load B tile (BK x BN)
        #pragma unroll
        for (int i = tid * 4; i < BK * BN; i += THREADS * 4) {
            int krow = i / BN;
            int ncol = i % BN;
            *reinterpret_cast<float4*>(&Bs[krow][ncol]) =
                *reinterpret_cast<const float4*>(&Bptr[(long)(k0 + krow) * N + ncol]);
        }
        __syncthreads();

        #pragma unroll
        for (int k = 0; k < BK; k++) {
            float regM[TM], regN[TN];
            #pragma unroll
            for (int m = 0; m < TM; m += 4) {
                float4 t = *reinterpret_cast<const float4*>(&As[k][threadRow * TM + m]);
                regM[m + 0] = t.x; regM[m + 1] = t.y; regM[m + 2] = t.z; regM[m + 3] = t.w;
            }
            #pragma unroll
            for (int n = 0; n < TN; n += 4) {
                float4 t = *reinterpret_cast<const float4*>(&Bs[k][threadCol * TN + n]);
                regN[n + 0] = t.x; regN[n + 1] = t.y; regN[n + 2] = t.z; regN[n + 3] = t.w;
            }
            #pragma unroll
            for (int m = 0; m < TM; m++)
                #pragma unroll
                for (int n = 0; n < TN; n++)
                    acc[m][n] += regM[m] * regN[n];
        }
        __syncthreads();
    }

    // Epilogue
    #pragma unroll
    for (int m = 0; m < TM; m++) {
        int grow = blockRow * BM + threadRow * TM + m;
        if (grow >= M) continue;
        #pragma unroll
        for (int n = 0; n < TN; n += 4) {
            int gcol = blockCol * BN + threadCol * TN + n;
            float4 t;
            t.x = acc[m][n + 0];
            t.y = acc[m][n + 1];
            t.z = acc[m][n + 2];
            t.w = acc[m][n + 3];
            if (BIAS) {
                t.x += bias[gcol + 0];
                t.y += bias[gcol + 1];
                t.z += bias[gcol + 2];
                t.w += bias[gcol + 3];
            }
            if (RELU) {
                t.x = fmaxf(t.x, 0.f);
                t.y = fmaxf(t.y, 0.f);
                t.z = fmaxf(t.z, 0.f);
                t.w = fmaxf(t.w, 0.f);
            }
            *reinterpret_cast<float4*>(&C[(long)grow * N + gcol]) = t;
        }
    }
}

// ---------------------------------------------------------------------------
// Kernel 4: x[n,i,d] = sum_j relu(g[n,i,d] + g[n,j,d] + b1[d])
// One thread per (n,d): 36 g-values live in registers; 36x36 inner loop.
// Loads are coalesced along d within each j-slice.
// ---------------------------------------------------------------------------
__global__ void pair_kernel(const float* __restrict__ b1) {
    int idx = blockIdx.x * blockDim.x + threadIdx.x;
    if (idx >= N_BATCH * D_DIM) return;
    int n = idx / D_DIM;
    int d = idx % D_DIM;

    const float* gn = g_g + (long)n * B_OBJ * D_DIM + d;
    float gv[B_OBJ];
    #pragma unroll
    for (int j = 0; j < B_OBJ; j++) gv[j] = gn[j * D_DIM];

    float bias = b1[d];
    float* xn = g_x + (long)n * B_OBJ * D_DIM + d;
    for (int i = 0; i < B_OBJ; i++) {
        float gi = gv[i] + bias;
        float s = 0.f;
        #pragma unroll
        for (int j = 0; j < B_OBJ; j++) s += fmaxf(gi + gv[j], 0.f);
        xn[i * D_DIM] = s;
    }
}

// ---------------------------------------------------------------------------
// Launch
// ---------------------------------------------------------------------------
extern "C" void kernel_launch(void* const* d_in, const int* in_sizes, int n_in,
                              void* d_out, int out_size) {
    const float* v  = (const float*)d_in[0];
    const float* q  = (const float*)d_in[1];
    const float* W1 = (const float*)d_in[2];
    const float* b1 = (const float*)d_in[3];
    const float* W2 = (const float*)d_in[4];
    const float* b2 = (const float*)d_in[5];
    const float* W3 = (const float*)d_in[6];
    const float* b3 = (const float*)d_in[7];
    float* out = (float*)d_out;

    float *p_u, *p_g, *p_x;
    cudaGetSymbolAddress((void**)&p_u, g_u);
    cudaGetSymbolAddress((void**)&p_g, g_g);
    cudaGetSymbolAddress((void**)&p_x, g_x);

    // 1) qe = relu(q @ W3 + b3)
    qe_kernel<<<(N_BATCH * D_DIM + 255) / 256, 256>>>(q, W3, b3);

    // 2) u = v * qe
    u_kernel<<<(NB * D_DIM + 255) / 256, 256>>>(v);

    // 3) g = u @ W1   (no bias, no relu)
    {
        dim3 grid(D_DIM / 128, (NB + 127) / 128);
        sgemm_kernel<128, 128, 8, 8, 8, false, false>
            <<<grid, 256>>>(NB, D_DIM, D_DIM, p_u, W1, nullptr, p_g);
    }

    // 4) x[n,i] = sum_j relu(g_i + g_j + b1)
    pair_kernel<<<(N_BATCH * D_DIM + 255) / 256, 256>>>(b1);

    // 5) out = relu(x @ W2 + b2)
    {
        dim3 grid(D_DIM / 128, (NB + 127) / 128);
        sgemm_kernel<128, 128, 8, 8, 8, true, true>
            <<<grid, 256>>>(NB, D_DIM, D_DIM, p_x, W2, b2, out);
    }
}

// round 3
// speedup vs baseline: 1.7407x; 1.7407x over previous
#include <cuda_runtime.h>
#include <cuda_bf16.h>
#include <cstdint>

// ---------------------------------------------------------------------------
// Problem dims (fixed by the dataset)
// ---------------------------------------------------------------------------
#define N_BATCH 32
#define B_OBJ   36
#define D_DIM   2048
#define Q_DIM   1024
#define NB      (N_BATCH * B_OBJ)   // 1152

// Scratch (device globals — no allocation allowed)
__device__ float g_qe [N_BATCH * D_DIM];   // relu(q @ W3 + b3)     (32, 2048)
__device__ float g_g  [NB * D_DIM];        // (v*qe) @ W1           (1152, 2048)
__device__ float g_x  [NB * D_DIM];        // sum_j relu(g_i+g_j+b1)
__device__ float g_W1t[D_DIM * D_DIM];     // W1^T (K-major rows)
__device__ float g_W2t[D_DIM * D_DIM];

// ---------------------------------------------------------------------------
// Helpers
// ---------------------------------------------------------------------------
__device__ __forceinline__ uint32_t smem_u32(const void* p) {
    uint32_t a;
    asm("{ .reg .u64 t; cvta.to.shared.u64 t, %1; cvt.u32.u64 %0, t; }"
        : "=r"(a) : "l"(p));
    return a;
}

__device__ __forceinline__ void ldmatrix_x4(uint32_t& r0, uint32_t& r1,
                                            uint32_t& r2, uint32_t& r3,
                                            uint32_t addr) {
    asm volatile("ldmatrix.sync.aligned.m8n8.x4.shared.b16 {%0,%1,%2,%3}, [%4];"
                 : "=r"(r0), "=r"(r1), "=r"(r2), "=r"(r3) : "r"(addr));
}

__device__ __forceinline__ void ldmatrix_x2(uint32_t& r0, uint32_t& r1,
                                            uint32_t addr) {
    asm volatile("ldmatrix.sync.aligned.m8n8.x2.shared.b16 {%0,%1}, [%2];"
                 : "=r"(r0), "=r"(r1) : "r"(addr));
}

__device__ __forceinline__ void mma_bf16(float& c0, float& c1, float& c2, float& c3,
                                         uint32_t a0, uint32_t a1, uint32_t a2, uint32_t a3,
                                         uint32_t b0, uint32_t b1) {
    asm volatile(
        "mma.sync.aligned.m16n8k16.row.col.f32.bf16.bf16.f32 "
        "{%0,%1,%2,%3}, {%4,%5,%6,%7}, {%8,%9}, {%0,%1,%2,%3};"
        : "+f"(c0), "+f"(c1), "+f"(c2), "+f"(c3)
        : "r"(a0), "r"(a1), "r"(a2), "r"(a3), "r"(b0), "r"(b1));
}

// Split a float into bf16 hi + bf16 lo (x ≈ hi + lo, 16 mantissa bits total)
__device__ __forceinline__ void split_pack(const float4 a, const float4 b,
                                           uint4& hi, uint4& lo) {
    __nv_bfloat16 hx = __float2bfloat16(a.x), hy = __float2bfloat16(a.y);
    __nv_bfloat16 hz = __float2bfloat16(a.z), hw = __float2bfloat16(a.w);
    __nv_bfloat16 gx = __float2bfloat16(b.x), gy = __float2bfloat16(b.y);
    __nv_bfloat16 gz = __float2bfloat16(b.z), gw = __float2bfloat16(b.w);
    __nv_bfloat16 lx = __float2bfloat16(a.x - __bfloat162float(hx));
    __nv_bfloat16 ly = __float2bfloat16(a.y - __bfloat162float(hy));
    __nv_bfloat16 lz = __float2bfloat16(a.z - __bfloat162float(hz));
    __nv_bfloat16 lw = __float2bfloat16(a.w - __bfloat162float(hw));
    __nv_bfloat16 mx = __float2bfloat16(b.x - __bfloat162float(gx));
    __nv_bfloat16 my = __float2bfloat16(b.y - __bfloat162float(gy));
    __nv_bfloat16 mz = __float2bfloat16(b.z - __bfloat162float(gz));
    __nv_bfloat16 mw = __float2bfloat16(b.w - __bfloat162float(gw));
    __nv_bfloat162 p;
    p = __nv_bfloat162(hx, hy); hi.x = *reinterpret_cast<uint32_t*>(&p);
    p = __nv_bfloat162(hz, hw); hi.y = *reinterpret_cast<uint32_t*>(&p);
    p = __nv_bfloat162(gx, gy); hi.z = *reinterpret_cast<uint32_t*>(&p);
    p = __nv_bfloat162(gz, gw); hi.w = *reinterpret_cast<uint32_t*>(&p);
    p = __nv_bfloat162(lx, ly); lo.x = *reinterpret_cast<uint32_t*>(&p);
    p = __nv_bfloat162(lz, lw); lo.y = *reinterpret_cast<uint32_t*>(&p);
    p = __nv_bfloat162(mx, my); lo.z = *reinterpret_cast<uint32_t*>(&p);
    p = __nv_bfloat162(mz, mw); lo.w = *reinterpret_cast<uint32_t*>(&p);
}

// ---------------------------------------------------------------------------
// Kernel 1: qe[n,d] = relu(sum_k q[n,k] * W3[k,d] + b3[d])
// ---------------------------------------------------------------------------
__global__ __launch_bounds__(256)
void qe_kernel(const float* __restrict__ q,
               const float* __restrict__ W3,
               const float* __restrict__ b3) {
    int gid = blockIdx.x * 256 + threadIdx.x;       // 0..16383
    int d  = gid & (D_DIM - 1);
    int n0 = (gid >> 11) * 4;
    float a0 = 0.f, a1 = 0.f, a2 = 0.f, a3 = 0.f;
    const float* q0 = q + (n0 + 0) * Q_DIM;
    const float* q1 = q + (n0 + 1) * Q_DIM;
    const float* q2 = q + (n0 + 2) * Q_DIM;
    const float* q3 = q + (n0 + 3) * Q_DIM;
    #pragma unroll 4
    for (int k = 0; k < Q_DIM; k++) {
        float w = W3[k * D_DIM + d];
        a0 += q0[k] * w; a1 += q1[k] * w; a2 += q2[k] * w; a3 += q3[k] * w;
    }
    float b = b3[d];
    g_qe[(n0 + 0) * D_DIM + d] = fmaxf(a0 + b, 0.f);
    g_qe[(n0 + 1) * D_DIM + d] = fmaxf(a1 + b, 0.f);
    g_qe[(n0 + 2) * D_DIM + d] = fmaxf(a2 + b, 0.f);
    g_qe[(n0 + 3) * D_DIM + d] = fmaxf(a3 + b, 0.f);
}

// ---------------------------------------------------------------------------
// Kernel 2: 2048x2048 transpose (W [K][N] -> Wt [N][K])
// ---------------------------------------------------------------------------
__global__ __launch_bounds__(256)
void transpose2048(const float* __restrict__ in, float* __restrict__ out) {
    __shared__ float tile[32][33];
    int x = blockIdx.x * 32 + threadIdx.x;
    int y = blockIdx.y * 32 + threadIdx.y;
    #pragma unroll
    for (int j = 0; j < 32; j += 8)
        tile[threadIdx.y + j][threadIdx.x] = in[(y + j) * D_DIM + x];
    __syncthreads();
    x = blockIdx.y * 32 + threadIdx.x;
    y = blockIdx.x * 32 + threadIdx.y;
    #pragma unroll
    for (int j = 0; j < 32; j += 8)
        out[(y + j) * D_DIM + x] = tile[threadIdx.x][threadIdx.y + j];
}

// ---------------------------------------------------------------------------
// GEMM: C[1152, 2048] = A[1152,2048] @ Bt^T,  Bt is [N][K] (K-contig rows).
// bf16 2-way split (Ah*Bh + Ah*Bl + Al*Bh), fp32 accum, mma.sync m16n8k16.
// CTA tile 128x128x32, 8 warps (2m x 4n), warp tile 64x32, double buffered.
// SMEM rows padded to 80B -> conflict-free ldmatrix.
// ---------------------------------------------------------------------------
constexpr int ROWB   = 80;                     // bytes per SMEM row (32 bf16 + pad)
constexpr int ARR    = 128 * ROWB;             // 10240 B, one 128x32 bf16 tile
constexpr int STAGE  = 4 * ARR;                // A_hi, A_lo, B_hi, B_lo
constexpr int SMEM_GEMM = 2 * STAGE;           // 81920 B

template<bool FUSE_U, bool BIASRELU>
__global__ __launch_bounds__(256, 1)
void bf16_gemm(const float* __restrict__ A,
               const float* __restrict__ qe,
               const float* __restrict__ Bt,
               const float* __restrict__ bias,
               float* __restrict__ C) {
    extern __shared__ char sm[];
    const uint32_t sbase = smem_u32(sm);

    const int tid  = threadIdx.x;
    const int wid  = tid >> 5;
    const int lane = tid & 31;
    const int wm   = wid >> 2;                 // 0..1
    const int wn   = wid & 3;                  // 0..3
    const int m0   = blockIdx.y * 128;
    const int n0   = blockIdx.x * 128;
    constexpr int K = 2048;
    constexpr int ITERS = K / 32;              // 64

    // Loader assignment: 2 (row, chunk) pairs each for A and B.
    // pair p (0..511): row = p>>2, chunk = p&3 (8 floats per chunk).
    const int r0c = tid >> 2, ch = tid & 3;    // pair t
    const int r1c = r0c + 64;                  // pair t+256
    const int qrow0 = FUSE_U ? (m0 + r0c) / B_OBJ : 0;
    const int qrow1 = FUSE_U ? (m0 + r1c) / B_OBJ : 0;

    const float* A0 = A + (size_t)(m0 + r0c) * K + ch * 8;
    const float* A1 = A + (size_t)(m0 + r1c) * K + ch * 8;
    const float* B0 = Bt + (size_t)(n0 + r0c) * K + ch * 8;
    const float* B1 = Bt + (size_t)(n0 + r1c) * K + ch * 8;
    const float* Q0 = FUSE_U ? qe + (size_t)qrow0 * D_DIM + ch * 8 : nullptr;
    const float* Q1 = FUSE_U ? qe + (size_t)qrow1 * D_DIM + ch * 8 : nullptr;

    float4 a0v, a1v, a2v, a3v, b0v, b1v, b2v, b3v;   // staging regs

    auto ldg = [&](int it) {
        const int kb = it * 32;
        a0v = *reinterpret_cast<const float4*>(A0 + kb);
        a1v = *reinterpret_cast<const float4*>(A0 + kb + 4);
        a2v = *reinterpret_cast<const float4*>(A1 + kb);
        a3v = *reinterpret_cast<const float4*>(A1 + kb + 4);
        b0v = *reinterpret_cast<const float4*>(B0 + kb);
        b1v = *reinterpret_cast<const float4*>(B0 + kb + 4);
        b2v = *reinterpret_cast<const float4*>(B1 + kb);
        b3v = *reinterpret_cast<const float4*>(B1 + kb + 4);
        if (FUSE_U) {
            float4 t;
            t = *reinterpret_cast<const float4*>(Q0 + kb);
            a0v.x *= t.x; a0v.y *= t.y; a0v.z *= t.z; a0v.w *= t.w;
            t = *reinterpret_cast<const float4*>(Q0 + kb + 4);
            a1v.x *= t.x; a1v.y *= t.y; a1v.z *= t.z; a1v.w *= t.w;
            t = *reinterpret_cast<const float4*>(Q1 + kb);
            a2v.x *= t.x; a2v.y *= t.y; a2v.z *= t.z; a2v.w *= t.w;
            t = *reinterpret_cast<const float4*>(Q1 + kb + 4);
            a3v.x *= t.x; a3v.y *= t.y; a3v.z *= t.z; a3v.w *= t.w;
        }
    };

    auto sts = [&](int s) {
        char* base = sm + s * STAGE;
        const int off0 = r0c * ROWB + ch * 16;
        const int off1 = r1c * ROWB + ch * 16;
        uint4 hi, lo;
        split_pack(a0v, a1v, hi, lo);
        *reinterpret_cast<uint4*>(base + off0)       = hi;   // A_hi
        *reinterpret_cast<uint4*>(base + ARR + off0) = lo;   // A_lo
        split_pack(a2v, a3v, hi, lo);
        *reinterpret_cast<uint4*>(base + off1)       = hi;
        *reinterpret_cast<uint4*>(base + ARR + off1) = lo;
        split_pack(b0v, b1v, hi, lo);
        *reinterpret_cast<uint4*>(base + 2 * ARR + off0) = hi;  // B_hi
        *reinterpret_cast<uint4*>(base + 3 * ARR + off0) = lo;  // B_lo
        split_pack(b2v, b3v, hi, lo);
        *reinterpret_cast<uint4*>(base + 2 * ARR + off1) = hi;
        *reinterpret_cast<uint4*>(base + 3 * ARR + off1) = lo;
    };

    // Per-lane ldmatrix byte offsets
    const uint32_t a_off = (lane & 15) * ROWB + ((lane >> 4) & 1) * 16;
    const uint32_t b_off = (lane & 7) * ROWB + ((lane >> 3) & 1) * 16;
    const uint32_t aw = (wm * 64) * ROWB + a_off;     // + mt*16*ROWB + kk*32
    const uint32_t bw = (wn * 32) * ROWB + b_off;     // + nt*8*ROWB  + kk*32

    float c[4][4][4];
    #pragma unroll
    for (int i = 0; i < 4; i++)
        #pragma unroll
        for (int j = 0; j < 4; j++)
            #pragma unroll
            for (int k = 0; k < 4; k++) c[i][j][k] = 0.f;

    // Prologue
    ldg(0);
    sts(0);
    __syncthreads();

    for (int it = 0; it < ITERS; it++) {
        const int s = it & 1;
        if (it + 1 < ITERS) ldg(it + 1);   // LDGs in flight over the MMA block

        const uint32_t sa = sbase + s * STAGE;
        #pragma unroll
        for (int kk = 0; kk < 2; kk++) {
            uint32_t ah[4][4], al[4][4], bh[4][2], bl[4][2];
            #pragma unroll
            for (int mt = 0; mt < 4; mt++) {
                uint32_t ad = sa + aw + mt * (16 * ROWB) + kk * 32;
                ldmatrix_x4(ah[mt][0], ah[mt][1], ah[mt][2], ah[mt][3], ad);
                ldmatrix_x4(al[mt][0], al[mt][1], al[mt][2], al[mt][3], ad + ARR);
            }
            #pragma unroll
            for (int nt = 0; nt < 4; nt++) {
                uint32_t bd = sa + 2 * ARR + bw + nt * (8 * ROWB) + kk * 32;
                ldmatrix_x2(bh[nt][0], bh[nt][1], bd);
                ldmatrix_x2(bl[nt][0], bl[nt][1], bd + ARR);
            }
            #pragma unroll
            for (int mt = 0; mt < 4; mt++)
                #pragma unroll
                for (int nt = 0; nt < 4; nt++) {
                    float* cc = c[mt][nt];
                    mma_bf16(cc[0], cc[1], cc[2], cc[3],
                             ah[mt][0], ah[mt][1], ah[mt][2], ah[mt][3],
                             bh[nt][0], bh[nt][1]);
                    mma_bf16(cc[0], cc[1], cc[2], cc[3],
                             ah[mt][0], ah[mt][1], ah[mt][2], ah[mt][3],
                             bl[nt][0], bl[nt][1]);
                    mma_bf16(cc[0], cc[1], cc[2], cc[3],
                             al[mt][0], al[mt][1], al[mt][2], al[mt][3],
                             bh[nt][0], bh[nt][1]);
                }
        }

        if (it + 1 < ITERS) {
            sts(s ^ 1);
            __syncthreads();
        }
    }

    // Epilogue: C frag (m16n8): lane holds (r=lane/4, col=2*(lane%4)) and r+8.
    const int er = lane >> 2;
    const int ec = (lane & 3) * 2;
    #pragma unroll
    for (int mt = 0; mt < 4; mt++) {
        const int grow = m0 + wm * 64 + mt * 16 + er;
        #pragma unroll
        for (int nt = 0; nt < 4; nt++) {
            const int gcol = n0 + wn * 32 + nt * 8 + ec;
            float2 lo_pair = make_float2(c[mt][nt][0], c[mt][nt][1]);
            float2 hi_pair = make_float2(c[mt][nt][2], c[mt][nt][3]);
            if (BIASRELU) {
                float bx = bias[gcol], by = bias[gcol + 1];
                lo_pair.x = fmaxf(lo_pair.x + bx, 0.f);
                lo_pair.y = fmaxf(lo_pair.y + by, 0.f);
                hi_pair.x = fmaxf(hi_pair.x + bx, 0.f);
                hi_pair.y = fmaxf(hi_pair.y + by, 0.f);
            }
            *reinterpret_cast<float2*>(C + (size_t)grow * D_DIM + gcol) = lo_pair;
            *reinterpret_cast<float2*>(C + (size_t)(grow + 8) * D_DIM + gcol) = hi_pair;
        }
    }
}

// ---------------------------------------------------------------------------
// Kernel: x[n,i,d] = sum_j relu(g[n,i,d] + g[n,j,d] + b1[d])
// ---------------------------------------------------------------------------
__global__ __launch_bounds__(576)
void pair_kernel(const float* __restrict__ b1) {
    __shared__ float sg[B_OBJ][64];
    int n  = blockIdx.y;
    int d0 = blockIdx.x * 64;
    int tid = threadIdx.x;

    const float* gbase = g_g + (size_t)n * B_OBJ * D_DIM + d0;
    #pragma unroll
    for (int l = tid; l < B_OBJ * 64; l += 576) {
        int j = l >> 6, dl = l & 63;
        sg[j][dl] = gbase[j * D_DIM + dl];
    }
    __syncthreads();

    int ig = tid / 64;        // 0..8
    int dl = tid % 64;
    float b = b1[d0 + dl];
    float gi[4], acc[4];
    #pragma unroll
    for (int ii = 0; ii < 4; ii++) {
        gi[ii] = sg[ig * 4 + ii][dl] + b;
        acc[ii] = 0.f;
    }
    #pragma unroll
    for (int j = 0; j < B_OBJ; j++) {
        float gj = sg[j][dl];
        #pragma unroll
        for (int ii = 0; ii < 4; ii++)
            acc[ii] += fmaxf(gi[ii] + gj, 0.f);
    }
    float* xbase = g_x + (size_t)n * B_OBJ * D_DIM + d0 + dl;
    #pragma unroll
    for (int ii = 0; ii < 4; ii++)
        xbase[(ig * 4 + ii) * D_DIM] = acc[ii];
}

// ---------------------------------------------------------------------------
// Launch
// ---------------------------------------------------------------------------
extern "C" void kernel_launch(void* const* d_in, const int* in_sizes, int n_in,
                              void* d_out, int out_size) {
    const float* v  = (const float*)d_in[0];
    const float* q  = (const float*)d_in[1];
    const float* W1 = (const float*)d_in[2];
    const float* b1 = (const float*)d_in[3];
    const float* W2 = (const float*)d_in[4];
    const float* b2 = (const float*)d_in[5];
    const float* W3 = (const float*)d_in[6];
    const float* b3 = (const float*)d_in[7];
    float* out = (float*)d_out;

    float *p_qe, *p_g, *p_x, *p_W1t, *p_W2t;
    cudaGetSymbolAddress((void**)&p_qe,  g_qe);
    cudaGetSymbolAddress((void**)&p_g,   g_g);
    cudaGetSymbolAddress((void**)&p_x,   g_x);
    cudaGetSymbolAddress((void**)&p_W1t, g_W1t);
    cudaGetSymbolAddress((void**)&p_W2t, g_W2t);

    cudaFuncSetAttribute(bf16_gemm<true,  false>,
                         cudaFuncAttributeMaxDynamicSharedMemorySize, SMEM_GEMM);
    cudaFuncSetAttribute(bf16_gemm<false, true>,
                         cudaFuncAttributeMaxDynamicSharedMemorySize, SMEM_GEMM);

    // 1) qe = relu(q @ W3 + b3)
    qe_kernel<<<64, 256>>>(q, W3, b3);

    // 2) transpose weights to K-major
    transpose2048<<<dim3(64, 64), dim3(32, 8)>>>(W1, p_W1t);
    transpose2048<<<dim3(64, 64), dim3(32, 8)>>>(W2, p_W2t);

    // 3) g = (v .* qe) @ W1   (u fused into A-load)
    bf16_gemm<true, false><<<dim3(16, 9), 256, SMEM_GEMM>>>(v, p_qe, p_W1t, nullptr, p_g);

    // 4) x[n,i] = sum_j relu(g_i + g_j + b1)
    pair_kernel<<<dim3(32, 32), 576>>>(b1);

    // 5) out = relu(x @ W2 + b2)
    bf16_gemm<false, true><<<dim3(16, 9), 256, SMEM_GEMM>>>(p_x, nullptr, p_W2t, b2, out);
}

// round 4
// speedup vs baseline: 1.9186x; 1.1022x over previous
#include <cuda_runtime.h>
#include <cuda_bf16.h>
#include <cstdint>

// ---------------------------------------------------------------------------
// Problem dims (fixed by the dataset)
// ---------------------------------------------------------------------------
#define N_BATCH 32
#define B_OBJ   36
#define D_DIM   2048
#define Q_DIM   1024
#define NB      (N_BATCH * B_OBJ)   // 1152

// Scratch (device globals)
__device__ float          g_qe [N_BATCH * D_DIM];
__device__ float          g_g  [NB * D_DIM];        // GEMM1 out (fp32, for pair)
__device__ __nv_bfloat16  g_uh [NB * D_DIM];        // (v*qe) hi
__device__ __nv_bfloat16  g_ul [NB * D_DIM];        // (v*qe) lo
__device__ __nv_bfloat16  g_xh [NB * D_DIM];        // pair-out hi
__device__ __nv_bfloat16  g_xl [NB * D_DIM];        // pair-out lo
__device__ __nv_bfloat16  g_W1h[D_DIM * D_DIM];     // W1^T hi  [N][K]
__device__ __nv_bfloat16  g_W1l[D_DIM * D_DIM];
__device__ __nv_bfloat16  g_W2h[D_DIM * D_DIM];
__device__ __nv_bfloat16  g_W2l[D_DIM * D_DIM];

// ---------------------------------------------------------------------------
// Helpers
// ---------------------------------------------------------------------------
__device__ __forceinline__ uint32_t smem_u32(const void* p) {
    uint32_t a;
    asm("{ .reg .u64 t; cvta.to.shared.u64 t, %1; cvt.u32.u64 %0, t; }"
        : "=r"(a) : "l"(p));
    return a;
}

__device__ __forceinline__ void ldmatrix_x4(uint32_t& r0, uint32_t& r1,
                                            uint32_t& r2, uint32_t& r3,
                                            uint32_t addr) {
    asm volatile("ldmatrix.sync.aligned.m8n8.x4.shared.b16 {%0,%1,%2,%3}, [%4];"
                 : "=r"(r0), "=r"(r1), "=r"(r2), "=r"(r3) : "r"(addr));
}

__device__ __forceinline__ void ldmatrix_x2(uint32_t& r0, uint32_t& r1,
                                            uint32_t addr) {
    asm volatile("ldmatrix.sync.aligned.m8n8.x2.shared.b16 {%0,%1}, [%2];"
                 : "=r"(r0), "=r"(r1) : "r"(addr));
}

__device__ __forceinline__ void mma_bf16(float& c0, float& c1, float& c2, float& c3,
                                         uint32_t a0, uint32_t a1, uint32_t a2, uint32_t a3,
                                         uint32_t b0, uint32_t b1) {
    asm volatile(
        "mma.sync.aligned.m16n8k16.row.col.f32.bf16.bf16.f32 "
        "{%0,%1,%2,%3}, {%4,%5,%6,%7}, {%8,%9}, {%0,%1,%2,%3};"
        : "+f"(c0), "+f"(c1), "+f"(c2), "+f"(c3)
        : "r"(a0), "r"(a1), "r"(a2), "r"(a3), "r"(b0), "r"(b1));
}

__device__ __forceinline__ void cp_async16(uint32_t dst, const void* src) {
    asm volatile("cp.async.cg.shared.global [%0], [%1], 16;"
                 :: "r"(dst), "l"(src) : "memory");
}
#define CP_COMMIT() asm volatile("cp.async.commit_group;" ::: "memory")
#define CP_WAIT2()  asm volatile("cp.async.wait_group 2;"  ::: "memory")

// Split fp32 -> bf16 hi + bf16 lo
__device__ __forceinline__ void split1(float x, __nv_bfloat16& h, __nv_bfloat16& l) {
    h = __float2bfloat16(x);
    l = __float2bfloat16(x - __bfloat162float(h));
}

// ---------------------------------------------------------------------------
// Kernel 1: qe[n,d] = relu(sum_k q[n,k] * W3[k,d] + b3[d])
// ---------------------------------------------------------------------------
__global__ __launch_bounds__(256)
void qe_kernel(const float* __restrict__ q,
               const float* __restrict__ W3,
               const float* __restrict__ b3) {
    int gid = blockIdx.x * 256 + threadIdx.x;       // 0..16383
    int d  = gid & (D_DIM - 1);
    int n0 = (gid >> 11) * 4;
    float a0 = 0.f, a1 = 0.f, a2 = 0.f, a3 = 0.f;
    const float* q0 = q + (n0 + 0) * Q_DIM;
    const float* q1 = q + (n0 + 1) * Q_DIM;
    const float* q2 = q + (n0 + 2) * Q_DIM;
    const float* q3 = q + (n0 + 3) * Q_DIM;
    #pragma unroll 4
    for (int k = 0; k < Q_DIM; k++) {
        float w = W3[k * D_DIM + d];
        a0 += q0[k] * w; a1 += q1[k] * w; a2 += q2[k] * w; a3 += q3[k] * w;
    }
    float b = b3[d];
    g_qe[(n0 + 0) * D_DIM + d] = fmaxf(a0 + b, 0.f);
    g_qe[(n0 + 1) * D_DIM + d] = fmaxf(a1 + b, 0.f);
    g_qe[(n0 + 2) * D_DIM + d] = fmaxf(a2 + b, 0.f);
    g_qe[(n0 + 3) * D_DIM + d] = fmaxf(a3 + b, 0.f);
}

// ---------------------------------------------------------------------------
// Kernel 2: fused transpose + bf16 split: W [K][N] -> Wt_hi/lo [N][K]
// ---------------------------------------------------------------------------
__global__ __launch_bounds__(256)
void wsplit(const float* __restrict__ in,
            __nv_bfloat16* __restrict__ oh,
            __nv_bfloat16* __restrict__ ol) {
    __shared__ float tile[32][33];
    int x = blockIdx.x * 32 + threadIdx.x;
    int y = blockIdx.y * 32 + threadIdx.y;
    #pragma unroll
    for (int j = 0; j < 32; j += 8)
        tile[threadIdx.y + j][threadIdx.x] = in[(y + j) * D_DIM + x];
    __syncthreads();
    x = blockIdx.y * 32 + threadIdx.x;   // k index in output
    y = blockIdx.x * 32 + threadIdx.y;   // n index in output
    #pragma unroll
    for (int j = 0; j < 32; j += 8) {
        float v = tile[threadIdx.x][threadIdx.y + j];
        __nv_bfloat16 h, l;
        split1(v, h, l);
        oh[(size_t)(y + j) * D_DIM + x] = h;
        ol[(size_t)(y + j) * D_DIM + x] = l;
    }
}

// ---------------------------------------------------------------------------
// Kernel 3: u = v * qe  -> split into g_uh / g_ul
// ---------------------------------------------------------------------------
__global__ __launch_bounds__(256)
void usplit(const float* __restrict__ v) {
    int idx4 = blockIdx.x * 256 + threadIdx.x;      // float4 index
    int idx = idx4 * 4;
    if (idx >= NB * D_DIM) return;
    int row = idx / D_DIM;
    int d   = idx & (D_DIM - 1);
    int n   = row / B_OBJ;
    float4 vv = *reinterpret_cast<const float4*>(v + idx);
    float4 qq = *reinterpret_cast<const float4*>(g_qe + n * D_DIM + d);
    float u0 = vv.x * qq.x, u1 = vv.y * qq.y, u2 = vv.z * qq.z, u3 = vv.w * qq.w;
    __nv_bfloat16 h0, h1, h2, h3, l0, l1, l2, l3;
    split1(u0, h0, l0); split1(u1, h1, l1);
    split1(u2, h2, l2); split1(u3, h3, l3);
    __nv_bfloat162 ph0(h0, h1), ph1(h2, h3), pl0(l0, l1), pl1(l2, l3);
    *reinterpret_cast<__nv_bfloat162*>(g_uh + idx)     = ph0;
    *reinterpret_cast<__nv_bfloat162*>(g_uh + idx + 2) = ph1;
    *reinterpret_cast<__nv_bfloat162*>(g_ul + idx)     = pl0;
    *reinterpret_cast<__nv_bfloat162*>(g_ul + idx + 2) = pl1;
}

// ---------------------------------------------------------------------------
// GEMM: C[1152,2048] = A @ B^T using pre-split bf16 hi/lo operands.
// A rows [M][K] (hi/lo), B rows [N][K] (hi/lo).  3-term: Ah*Bh + Ah*Bl + Al*Bh.
// CTA 128x128x32, 512 threads (16 warps, 4x4), warp tile 32x32.
// cp.async 4-stage pipeline. SMEM rows padded to 80B (conflict-free ldmatrix).
// ---------------------------------------------------------------------------
constexpr int ROWB   = 80;
constexpr int TILEB  = 128 * ROWB;        // 10240
constexpr int STAGEB = 4 * TILEB;         // 40960 (Ah, Al, Bh, Bl)
constexpr int SMEM_GEMM = 4 * STAGEB;     // 163840

template<bool BIASRELU>
__global__ __launch_bounds__(512, 1)
void bf16_gemm(const __nv_bfloat16* __restrict__ Ah,
               const __nv_bfloat16* __restrict__ Al,
               const __nv_bfloat16* __restrict__ Bh,
               const __nv_bfloat16* __restrict__ Bl,
               const float* __restrict__ bias,
               float* __restrict__ C) {
    extern __shared__ char sm[];
    const uint32_t sbase = smem_u32(sm);

    const int tid  = threadIdx.x;
    const int wid  = tid >> 5;
    const int lane = tid & 31;
    const int wm   = wid >> 2;                 // 0..3
    const int wn   = wid & 3;                  // 0..3
    const int m0   = blockIdx.y * 128;
    const int n0   = blockIdx.x * 128;
    constexpr int K = 2048;
    constexpr int ITERS = K / 32;              // 64

    // cp.async assignment: row = tid>>2, chunk c = tid&3 (16B each), all 4 tiles
    const int lr = tid >> 2;
    const int lc = tid & 3;
    const char* gAh = (const char*)(Ah + (size_t)(m0 + lr) * K) + lc * 16;
    const char* gAl = (const char*)(Al + (size_t)(m0 + lr) * K) + lc * 16;
    const char* gBh = (const char*)(Bh + (size_t)(n0 + lr) * K) + lc * 16;
    const char* gBl = (const char*)(Bl + (size_t)(n0 + lr) * K) + lc * 16;
    const uint32_t sdst = sbase + lr * ROWB + lc * 16;

    auto issue = [&](int it) {
        if (it < ITERS) {
            const uint32_t st = (it & 3) * STAGEB;
            const int gk = it * 64;            // byte offset along K (32 bf16)
            cp_async16(sdst + st,             gAh + gk);
            cp_async16(sdst + st + TILEB,     gAl + gk);
            cp_async16(sdst + st + 2 * TILEB, gBh + gk);
            cp_async16(sdst + st + 3 * TILEB, gBl + gk);
        }
        CP_COMMIT();
    };

    // ldmatrix per-lane offsets
    const uint32_t a_off = (wm * 32 + (lane & 15)) * ROWB + ((lane >> 4) & 1) * 16;
    const uint32_t b_off = (wn * 32 + (lane & 7)) * ROWB + ((lane >> 3) & 1) * 16;

    float c[2][4][4];
    #pragma unroll
    for (int i = 0; i < 2; i++)
        #pragma unroll
        for (int j = 0; j < 4; j++)
            #pragma unroll
            for (int k = 0; k < 4; k++) c[i][j][k] = 0.f;

    issue(0); issue(1); issue(2);

    for (int it = 0; it < ITERS; it++) {
        CP_WAIT2();
        __syncthreads();
        issue(it + 3);

        const uint32_t sa = sbase + (it & 3) * STAGEB;
        #pragma unroll
        for (int kk = 0; kk < 2; kk++) {
            uint32_t ah[2][4], al[2][4], bh[4][2], bl[4][2];
            #pragma unroll
            for (int mt = 0; mt < 2; mt++) {
                uint32_t ad = sa + a_off + mt * (16 * ROWB) + kk * 32;
                ldmatrix_x4(ah[mt][0], ah[mt][1], ah[mt][2], ah[mt][3], ad);
                ldmatrix_x4(al[mt][0], al[mt][1], al[mt][2], al[mt][3], ad + TILEB);
            }
            #pragma unroll
            for (int nt = 0; nt < 4; nt++) {
                uint32_t bd = sa + 2 * TILEB + b_off + nt * (8 * ROWB) + kk * 32;
                ldmatrix_x2(bh[nt][0], bh[nt][1], bd);
                ldmatrix_x2(bl[nt][0], bl[nt][1], bd + TILEB);
            }
            #pragma unroll
            for (int mt = 0; mt < 2; mt++)
                #pragma unroll
                for (int nt = 0; nt < 4; nt++) {
                    float* cc = c[mt][nt];
                    mma_bf16(cc[0], cc[1], cc[2], cc[3],
                             ah[mt][0], ah[mt][1], ah[mt][2], ah[mt][3],
                             bh[nt][0], bh[nt][1]);
                    mma_bf16(cc[0], cc[1], cc[2], cc[3],
                             ah[mt][0], ah[mt][1], ah[mt][2], ah[mt][3],
                             bl[nt][0], bl[nt][1]);
                    mma_bf16(cc[0], cc[1], cc[2], cc[3],
                             al[mt][0], al[mt][1], al[mt][2], al[mt][3],
                             bh[nt][0], bh[nt][1]);
                }
        }
        __syncthreads();
    }

    // Epilogue
    const int er = lane >> 2;
    const int ec = (lane & 3) * 2;
    #pragma unroll
    for (int mt = 0; mt < 2; mt++) {
        const int grow = m0 + wm * 32 + mt * 16 + er;
        #pragma unroll
        for (int nt = 0; nt < 4; nt++) {
            const int gcol = n0 + wn * 32 + nt * 8 + ec;
            float2 p0 = make_float2(c[mt][nt][0], c[mt][nt][1]);
            float2 p1 = make_float2(c[mt][nt][2], c[mt][nt][3]);
            if (BIASRELU) {
                float bx = bias[gcol], by = bias[gcol + 1];
                p0.x = fmaxf(p0.x + bx, 0.f);
                p0.y = fmaxf(p0.y + by, 0.f);
                p1.x = fmaxf(p1.x + bx, 0.f);
                p1.y = fmaxf(p1.y + by, 0.f);
            }
            *reinterpret_cast<float2*>(C + (size_t)grow * D_DIM + gcol) = p0;
            *reinterpret_cast<float2*>(C + (size_t)(grow + 8) * D_DIM + gcol) = p1;
        }
    }
}

// ---------------------------------------------------------------------------
// Kernel: x[n,i,d] = sum_j relu(g[n,i,d] + g[n,j,d] + b1[d]); emit bf16 split.
// ---------------------------------------------------------------------------
__global__ __launch_bounds__(576)
void pair_kernel(const float* __restrict__ b1) {
    __shared__ float sg[B_OBJ][64];
    int n  = blockIdx.y;
    int d0 = blockIdx.x * 64;
    int tid = threadIdx.x;

    const float* gbase = g_g + (size_t)n * B_OBJ * D_DIM + d0;
    #pragma unroll
    for (int l = tid; l < B_OBJ * 64; l += 576) {
        int j = l >> 6, dl = l & 63;
        sg[j][dl] = gbase[j * D_DIM + dl];
    }
    __syncthreads();

    int ig = tid / 64;        // 0..8
    int dl = tid % 64;
    float b = b1[d0 + dl];
    float gi[4], acc[4];
    #pragma unroll
    for (int ii = 0; ii < 4; ii++) {
        gi[ii] = sg[ig * 4 + ii][dl] + b;
        acc[ii] = 0.f;
    }
    #pragma unroll
    for (int j = 0; j < B_OBJ; j++) {
        float gj = sg[j][dl];
        #pragma unroll
        for (int ii = 0; ii < 4; ii++)
            acc[ii] += fmaxf(gi[ii] + gj, 0.f);
    }
    size_t obase = (size_t)n * B_OBJ * D_DIM + d0 + dl;
    #pragma unroll
    for (int ii = 0; ii < 4; ii++) {
        __nv_bfloat16 h, l;
        split1(acc[ii], h, l);
        g_xh[obase + (size_t)(ig * 4 + ii) * D_DIM] = h;
        g_xl[obase + (size_t)(ig * 4 + ii) * D_DIM] = l;
    }
}

// ---------------------------------------------------------------------------
// Launch
// ---------------------------------------------------------------------------
extern "C" void kernel_launch(void* const* d_in, const int* in_sizes, int n_in,
                              void* d_out, int out_size) {
    const float* v  = (const float*)d_in[0];
    const float* q  = (const float*)d_in[1];
    const float* W1 = (const float*)d_in[2];
    const float* b1 = (const float*)d_in[3];
    const float* W2 = (const float*)d_in[4];
    const float* b2 = (const float*)d_in[5];
    const float* W3 = (const float*)d_in[6];
    const float* b3 = (const float*)d_in[7];
    float* out = (float*)d_out;

    float *p_g;
    __nv_bfloat16 *p_uh, *p_ul, *p_xh, *p_xl, *p_W1h, *p_W1l, *p_W2h, *p_W2l;
    cudaGetSymbolAddress((void**)&p_g,   g_g);
    cudaGetSymbolAddress((void**)&p_uh,  g_uh);
    cudaGetSymbolAddress((void**)&p_ul,  g_ul);
    cudaGetSymbolAddress((void**)&p_xh,  g_xh);
    cudaGetSymbolAddress((void**)&p_xl,  g_xl);
    cudaGetSymbolAddress((void**)&p_W1h, g_W1h);
    cudaGetSymbolAddress((void**)&p_W1l, g_W1l);
    cudaGetSymbolAddress((void**)&p_W2h, g_W2h);
    cudaGetSymbolAddress((void**)&p_W2l, g_W2l);

    cudaFuncSetAttribute(bf16_gemm<false>,
                         cudaFuncAttributeMaxDynamicSharedMemorySize, SMEM_GEMM);
    cudaFuncSetAttribute(bf16_gemm<true>,
                         cudaFuncAttributeMaxDynamicSharedMemorySize, SMEM_GEMM);

    // 1) qe = relu(q @ W3 + b3)
    qe_kernel<<<64, 256>>>(q, W3, b3);

    // 2) transpose + split weights
    wsplit<<<dim3(64, 64), dim3(32, 8)>>>(W1, p_W1h, p_W1l);
    wsplit<<<dim3(64, 64), dim3(32, 8)>>>(W2, p_W2h, p_W2l);

    // 3) u = v * qe, split to bf16 hi/lo
    usplit<<<(NB * D_DIM / 4 + 255) / 256, 256>>>(v);

    // 4) g = u @ W1^T   (fp32 out)
    bf16_gemm<false><<<dim3(16, 9), 512, SMEM_GEMM>>>(p_uh, p_ul, p_W1h, p_W1l,
                                                      nullptr, p_g);

    // 5) x = sum_j relu(g_i + g_j + b1), split to bf16 hi/lo
    pair_kernel<<<dim3(32, 32), 576>>>(b1);

    // 6) out = relu(x @ W2^T + b2)
    bf16_gemm<true><<<dim3(16, 9), 512, SMEM_GEMM>>>(p_xh, p_xl, p_W2h, p_W2l,
                                                     b2, out);
}